// round 7
// baseline (speedup 1.0000x reference)
#include <cuda_runtime.h>
#include <cuda_bf16.h>
#include <math.h>

#define NNODES 50000
#define NE     800000
#define DMODEL 96
#define NHEADS 3
#define NHID   32

// ---------------- scratch (static __device__, no allocation) ----------------
__device__ float g_h0[NNODES * 8];          // tanh(x@W1+b1)
__device__ float g_h1[NNODES * DMODEL];     // layer-1 output
__device__ float g_q[NNODES * DMODEL];
__device__ float g_kv[NNODES * 2 * DMODEL]; // interleaved [k(96) | v(96)] per node
__device__ float g_skip[NNODES * DMODEL];
__device__ int   g_deg[NNODES + 64];
__device__ int   g_off[NNODES + 64];
__device__ int   g_cursor[NNODES + 64];
__device__ int   g_bsum[128];
__device__ int2  g_edges[NE];               // (src, eid) sorted by dst

// ---------------- tiny pre-MLP: h0 = tanh(x@W1 + b1) ----------------
__global__ void pre_mlp(const float* __restrict__ x, const float* __restrict__ W1,
                        const float* __restrict__ b1) {
    int t = blockIdx.x * blockDim.x + threadIdx.x;
    if (t >= NNODES * 8) return;
    int n = t >> 3, j = t & 7;
    float acc = b1[j];
#pragma unroll
    for (int f = 0; f < 16; f++) acc += x[n * 16 + f] * W1[f * 8 + j];
    g_h0[t] = tanhf(acc);
}

// ---------------- counting sort by dst ----------------
__global__ void zero_deg() {
    int t = blockIdx.x * blockDim.x + threadIdx.x;
    if (t < NNODES) g_deg[t] = 0;
}

__global__ void hist_kernel(const int* __restrict__ ei) {
    int e = blockIdx.x * blockDim.x + threadIdx.x;
    if (e < NE) atomicAdd(&g_deg[ei[NE + e]], 1);
}

// per-1024 block exclusive scan + block totals
__global__ void scan_block() {
    __shared__ int sh[1024];
    int gid = blockIdx.x * 1024 + threadIdx.x;
    int v = (gid < NNODES) ? g_deg[gid] : 0;
    sh[threadIdx.x] = v;
    __syncthreads();
    for (int s = 1; s < 1024; s <<= 1) {
        int t = 0;
        if ((int)threadIdx.x >= s) t = sh[threadIdx.x - s];
        __syncthreads();
        sh[threadIdx.x] += t;
        __syncthreads();
    }
    if (gid < NNODES) g_off[gid] = sh[threadIdx.x] - v;  // exclusive
    if (threadIdx.x == 1023) g_bsum[blockIdx.x] = sh[1023];
}

// warp-level exclusive scan of the <=64 block sums (nb = 49 here)
__global__ void scan_bsum(int nb) {
    int lane = threadIdx.x;  // 64 threads
    int v = (lane < nb) ? g_bsum[lane] : 0;
    // inclusive scan over 64 lanes via two-warp shared-memory scan
    __shared__ int sh[64];
    sh[lane] = v;
    __syncthreads();
    for (int s = 1; s < 64; s <<= 1) {
        int t = (lane >= s) ? sh[lane - s] : 0;
        __syncthreads();
        sh[lane] += t;
        __syncthreads();
    }
    if (lane < nb) g_bsum[lane] = sh[lane] - v;  // exclusive
}

__global__ void scan_add() {
    int gid = blockIdx.x * blockDim.x + threadIdx.x;
    if (gid < NNODES) {
        int v = g_off[gid] + g_bsum[gid >> 10];
        g_off[gid] = v;
        g_cursor[gid] = v;
    }
    if (gid == 0) g_off[NNODES] = NE;
}

__global__ void scatter_kernel(const int* __restrict__ ei) {
    int e = blockIdx.x * blockDim.x + threadIdx.x;
    if (e < NE) {
        int dst = ei[NE + e];
        int pos = atomicAdd(&g_cursor[dst], 1);
        g_edges[pos] = make_int2(ei[e], e);
    }
}

// ---------------- node transform: q / k / v / skip = h @ W + b ----------------
// block: (96,2) threads. 32 nodes/block (16 per thread-row), 16-node register blocking.
template <int FI>
__global__ void node_transform(const float* __restrict__ h,
                               const float* __restrict__ Wq, const float* __restrict__ bq,
                               const float* __restrict__ Wk, const float* __restrict__ bk,
                               const float* __restrict__ Wv, const float* __restrict__ bv,
                               const float* __restrict__ Ws, const float* __restrict__ bs) {
    const int d = threadIdx.x;   // 0..95
    const int r = threadIdx.y;   // 0..1
    __shared__ float sh[32][FI + (FI % 2 == 0 ? 1 : 0)];
    const int nodeBlock = blockIdx.x * 32;

    for (int idx = threadIdx.y * 96 + threadIdx.x; idx < 32 * FI; idx += 192) {
        int nn = idx / FI, ff = idx - nn * FI;
        int node = nodeBlock + nn;
        sh[nn][ff] = (node < NNODES) ? h[node * FI + ff] : 0.f;
    }
    __syncthreads();

    float aq[16], ak[16], av[16], as_[16];
    const float _bq = bq[d], _bk = bk[d], _bv = bv[d], _bs = bs[d];
#pragma unroll
    for (int i = 0; i < 16; i++) { aq[i] = _bq; ak[i] = _bk; av[i] = _bv; as_[i] = _bs; }

    for (int f = 0; f < FI; f++) {
        float wq = Wq[f * 96 + d], wk = Wk[f * 96 + d];
        float wv = Wv[f * 96 + d], ws = Ws[f * 96 + d];
#pragma unroll
        for (int i = 0; i < 16; i++) {
            float hv = sh[r * 16 + i][f];
            aq[i] += hv * wq; ak[i] += hv * wk; av[i] += hv * wv; as_[i] += hv * ws;
        }
    }

#pragma unroll
    for (int i = 0; i < 16; i++) {
        int node = nodeBlock + r * 16 + i;
        if (node < NNODES) {
            g_q[node * 96 + d]        = aq[i];
            g_kv[node * 192 + d]      = ak[i];
            g_kv[node * 192 + 96 + d] = av[i];
            g_skip[node * 96 + d]     = as_[i];
        }
    }
}

// ---------------- edge aggregation: warp per destination, online softmax ------
// One warp per destination node, We weights in registers, 2-stage software
// pipeline (edge e+1's k/v/edge_attr loads issued before edge e's math).
// Scalar k/v loads: lanes of a warp cover one 128B line per head -> coalesced.
__global__ void edge_agg(const float* __restrict__ ea, const float* __restrict__ We,
                         float* __restrict__ out) {
    const int warp = (blockIdx.x * blockDim.x + threadIdx.x) >> 5;
    const int lane = threadIdx.x & 31;
    if (warp >= NNODES) return;
    const int n = warp;

    // per-lane We columns: we[h][r] = We[r*96 + h*32 + lane]
    float we[NHEADS][4];
#pragma unroll
    for (int h = 0; h < NHEADS; h++)
#pragma unroll
        for (int r = 0; r < 4; r++)
            we[h][r] = We[r * 96 + h * 32 + lane];

    float qh[NHEADS], m[NHEADS], s[NHEADS], acc[NHEADS], skp[NHEADS];
#pragma unroll
    for (int h = 0; h < NHEADS; h++) {
        qh[h]  = g_q[n * 96 + h * 32 + lane];
        skp[h] = g_skip[n * 96 + h * 32 + lane];
        m[h] = -1e30f; s[h] = 0.f; acc[h] = 0.f;
    }

    const int e0 = g_off[n], e1 = g_off[n + 1];
    const float invs = 0.17677669529663687f;  // 1/sqrt(32)

    // ---- pipeline stage registers (scalar k/v + edge attr) ----
    float4 eav;
    float kk[NHEADS], vv[NHEADS];

    auto load_edge = [&](int e, float4& _eav, float* _k, float* _v) {
        int2 se = g_edges[e];
        const float* kvp = g_kv + (long)se.x * 192;
        _eav = reinterpret_cast<const float4*>(ea)[se.y];
#pragma unroll
        for (int h = 0; h < NHEADS; h++) {
            int di = h * 32 + lane;
            _k[h] = __ldg(kvp + di);
            _v[h] = __ldg(kvp + 96 + di);
        }
    };

    if (e0 < e1) load_edge(e0, eav, kk, vv);

    for (int e = e0; e < e1; e++) {
        // prefetch next edge's payload before consuming current
        float4 n_eav;
        float n_k[NHEADS], n_v[NHEADS];
        if (e + 1 < e1) load_edge(e + 1, n_eav, n_k, n_v);

#pragma unroll
        for (int h = 0; h < NHEADS; h++) {
            float eev = eav.x * we[h][0] + eav.y * we[h][1] +
                        eav.z * we[h][2] + eav.w * we[h][3];
            float kval = kk[h] + eev;
            float vval = vv[h] + eev;
            float p = qh[h] * kval;
            p += __shfl_xor_sync(0xffffffffu, p, 16);
            p += __shfl_xor_sync(0xffffffffu, p, 8);
            p += __shfl_xor_sync(0xffffffffu, p, 4);
            p += __shfl_xor_sync(0xffffffffu, p, 2);
            p += __shfl_xor_sync(0xffffffffu, p, 1);
            float logit = p * invs;
            float nm = fmaxf(m[h], logit);
            float c  = __expf(m[h] - nm);   // 1 if no new max; 0 on first edge
            float pe = __expf(logit - nm);
            s[h]   = s[h] * c + pe;
            acc[h] = acc[h] * c + pe * vval;
            m[h] = nm;
        }

        eav = n_eav;
#pragma unroll
        for (int h = 0; h < NHEADS; h++) { kk[h] = n_k[h]; vv[h] = n_v[h]; }
    }

#pragma unroll
    for (int h = 0; h < NHEADS; h++) {
        float o = acc[h] / (s[h] + 1e-16f) + skp[h];
        out[n * 96 + h * 32 + lane] = tanhf(o);
    }
}

// ---------------- launch ----------------
extern "C" void kernel_launch(void* const* d_in, const int* in_sizes, int n_in,
                              void* d_out, int out_size) {
    const float* x   = (const float*)d_in[0];
    const int*   ei  = (const int*)d_in[1];
    const float* ea  = (const float*)d_in[2];
    const float* W1  = (const float*)d_in[3];
    const float* b1  = (const float*)d_in[4];
    const float* Wq1 = (const float*)d_in[5];
    const float* bq1 = (const float*)d_in[6];
    const float* Wk1 = (const float*)d_in[7];
    const float* bk1 = (const float*)d_in[8];
    const float* Wv1 = (const float*)d_in[9];
    const float* bv1 = (const float*)d_in[10];
    const float* We1 = (const float*)d_in[11];
    const float* Ws1 = (const float*)d_in[12];
    const float* bs1 = (const float*)d_in[13];
    const float* Wq2 = (const float*)d_in[14];
    const float* bq2 = (const float*)d_in[15];
    const float* Wk2 = (const float*)d_in[16];
    const float* bk2 = (const float*)d_in[17];
    const float* Wv2 = (const float*)d_in[18];
    const float* bv2 = (const float*)d_in[19];
    const float* We2 = (const float*)d_in[20];
    const float* Ws2 = (const float*)d_in[21];
    const float* bs2 = (const float*)d_in[22];
    float* out = (float*)d_out;

    float* h0; cudaGetSymbolAddress((void**)&h0, g_h0);
    float* h1; cudaGetSymbolAddress((void**)&h1, g_h1);

    const int nScanBlocks = (NNODES + 1023) / 1024;

    // pre-MLP
    pre_mlp<<<(NNODES * 8 + 255) / 256, 256>>>(x, W1, b1);

    // counting sort by dst (CSR build)
    zero_deg<<<(NNODES + 255) / 256, 256>>>();
    hist_kernel<<<(NE + 255) / 256, 256>>>(ei);
    scan_block<<<nScanBlocks, 1024>>>();
    scan_bsum<<<1, 64>>>(nScanBlocks);
    scan_add<<<(NNODES + 255) / 256, 256>>>();
    scatter_kernel<<<(NE + 255) / 256, 256>>>(ei);

    dim3 tfb(96, 2);
    const int nTfBlocks = (NNODES + 31) / 32;
    const int nAggBlocks = (NNODES * 32 + 255) / 256;

    // layer 1
    node_transform<8><<<nTfBlocks, tfb>>>(h0, Wq1, bq1, Wk1, bk1, Wv1, bv1, Ws1, bs1);
    edge_agg<<<nAggBlocks, 256>>>(ea, We1, h1);

    // layer 2
    node_transform<96><<<nTfBlocks, tfb>>>(h1, Wq2, bq2, Wk2, bk2, Wv2, bv2, Ws2, bs2);
    edge_agg<<<nAggBlocks, 256>>>(ea, We2, out);
}

// round 9
// speedup vs baseline: 1.1033x; 1.1033x over previous
#include <cuda_runtime.h>
#include <cuda_bf16.h>
#include <math.h>

#define NNODES 50000
#define NE     800000
#define DMODEL 96
#define NHEADS 3
#define NHID   32

// ---------------- scratch (static __device__, no allocation) ----------------
__device__ float g_h0[NNODES * 8];          // tanh(x@W1+b1)
__device__ float g_h1[NNODES * DMODEL];     // layer-1 output
__device__ float g_q[NNODES * DMODEL];
__device__ float g_kv[NNODES * 2 * DMODEL]; // interleaved [k(96) | v(96)] per node
__device__ float g_skip[NNODES * DMODEL];
__device__ int   g_deg[NNODES + 64];
__device__ int   g_off[NNODES + 64];
__device__ int   g_cursor[NNODES + 64];
__device__ int   g_bsum[128];
__device__ int2  g_edges[NE];               // (src, eid) sorted by dst

// packed fp32x2 fma (Blackwell): d = a*b + c, exact fp32 semantics per lane
__device__ __forceinline__ float2 ffma2(float2 a, float2 b, float2 c) {
    unsigned long long ua = *reinterpret_cast<unsigned long long*>(&a);
    unsigned long long ub = *reinterpret_cast<unsigned long long*>(&b);
    unsigned long long uc = *reinterpret_cast<unsigned long long*>(&c);
    unsigned long long ud;
    asm("fma.rn.f32x2 %0, %1, %2, %3;" : "=l"(ud) : "l"(ua), "l"(ub), "l"(uc));
    return *reinterpret_cast<float2*>(&ud);
}

// ---------------- tiny pre-MLP: h0 = tanh(x@W1 + b1) ----------------
__global__ void pre_mlp(const float* __restrict__ x, const float* __restrict__ W1,
                        const float* __restrict__ b1) {
    int t = blockIdx.x * blockDim.x + threadIdx.x;
    if (t >= NNODES * 8) return;
    int n = t >> 3, j = t & 7;
    float acc = b1[j];
#pragma unroll
    for (int f = 0; f < 16; f++) acc += x[n * 16 + f] * W1[f * 8 + j];
    g_h0[t] = tanhf(acc);
}

// ---------------- counting sort by dst ----------------
__global__ void zero_deg() {
    int t = blockIdx.x * blockDim.x + threadIdx.x;
    if (t < NNODES) g_deg[t] = 0;
}

__global__ void hist_kernel(const int* __restrict__ ei) {
    int e = blockIdx.x * blockDim.x + threadIdx.x;
    if (e < NE) atomicAdd(&g_deg[ei[NE + e]], 1);
}

// per-1024 block exclusive scan + block totals
__global__ void scan_block() {
    __shared__ int sh[1024];
    int gid = blockIdx.x * 1024 + threadIdx.x;
    int v = (gid < NNODES) ? g_deg[gid] : 0;
    sh[threadIdx.x] = v;
    __syncthreads();
    for (int s = 1; s < 1024; s <<= 1) {
        int t = 0;
        if ((int)threadIdx.x >= s) t = sh[threadIdx.x - s];
        __syncthreads();
        sh[threadIdx.x] += t;
        __syncthreads();
    }
    if (gid < NNODES) g_off[gid] = sh[threadIdx.x] - v;  // exclusive
    if (threadIdx.x == 1023) g_bsum[blockIdx.x] = sh[1023];
}

// scan of the <=64 block sums (nb = 49 here)
__global__ void scan_bsum(int nb) {
    int lane = threadIdx.x;  // 64 threads
    int v = (lane < nb) ? g_bsum[lane] : 0;
    __shared__ int sh[64];
    sh[lane] = v;
    __syncthreads();
    for (int s = 1; s < 64; s <<= 1) {
        int t = (lane >= s) ? sh[lane - s] : 0;
        __syncthreads();
        sh[lane] += t;
        __syncthreads();
    }
    if (lane < nb) g_bsum[lane] = sh[lane] - v;  // exclusive
}

__global__ void scan_add() {
    int gid = blockIdx.x * blockDim.x + threadIdx.x;
    if (gid < NNODES) {
        int v = g_off[gid] + g_bsum[gid >> 10];
        g_off[gid] = v;
        g_cursor[gid] = v;
    }
    if (gid == 0) g_off[NNODES] = NE;
}

__global__ void scatter_kernel(const int* __restrict__ ei) {
    int e = blockIdx.x * blockDim.x + threadIdx.x;
    if (e < NE) {
        int dst = ei[NE + e];
        int pos = atomicAdd(&g_cursor[dst], 1);
        g_edges[pos] = make_int2(ei[e], e);
    }
}

// ---------------- node transform: q / k / v / skip = h @ W + b ----------------
// block: (96,2) threads, 32 nodes/block. Packed f32x2 math: each thread owns
// 8 node-pairs x 4 output streams. smem holds h transposed as [f][node-pair]
// so one LDS.64 yields a node-pair, broadcast across the 96 d-threads.
template <int FI>
__global__ void node_transform(const float* __restrict__ h,
                               const float* __restrict__ Wq, const float* __restrict__ bq,
                               const float* __restrict__ Wk, const float* __restrict__ bk,
                               const float* __restrict__ Wv, const float* __restrict__ bv,
                               const float* __restrict__ Ws, const float* __restrict__ bs) {
    const int d = threadIdx.x;   // 0..95 output dim
    const int r = threadIdx.y;   // 0..1 node half
    __shared__ float2 sh2[FI][17];        // [feature][node-pair], +1 pad
    const int nodeBlock = blockIdx.x * 32;

    // coalesced global read (node-major), transposed smem write
    for (int idx = threadIdx.y * 96 + threadIdx.x; idx < 32 * FI; idx += 192) {
        int nn = idx / FI, ff = idx - nn * FI;
        int node = nodeBlock + nn;
        float v = (node < NNODES) ? h[node * FI + ff] : 0.f;
        reinterpret_cast<float*>(&sh2[ff][nn >> 1])[nn & 1] = v;
    }
    __syncthreads();

    float2 aq[8], ak[8], av[8], as_[8];
    const float _bq = bq[d], _bk = bk[d], _bv = bv[d], _bs = bs[d];
#pragma unroll
    for (int i = 0; i < 8; i++) {
        aq[i] = make_float2(_bq, _bq); ak[i] = make_float2(_bk, _bk);
        av[i] = make_float2(_bv, _bv); as_[i] = make_float2(_bs, _bs);
    }

    for (int f = 0; f < FI; f++) {
        float wq = Wq[f * 96 + d], wk = Wk[f * 96 + d];
        float wv = Wv[f * 96 + d], ws = Ws[f * 96 + d];
        float2 wq2 = make_float2(wq, wq), wk2 = make_float2(wk, wk);
        float2 wv2 = make_float2(wv, wv), ws2 = make_float2(ws, ws);
#pragma unroll
        for (int i = 0; i < 8; i++) {
            float2 hv = sh2[f][r * 8 + i];
            aq[i] = ffma2(hv, wq2, aq[i]);
            ak[i] = ffma2(hv, wk2, ak[i]);
            av[i] = ffma2(hv, wv2, av[i]);
            as_[i] = ffma2(hv, ws2, as_[i]);
        }
    }

#pragma unroll
    for (int i = 0; i < 8; i++) {
        int node0 = nodeBlock + r * 16 + 2 * i;
        int node1 = node0 + 1;
        if (node0 < NNODES) {
            g_q[node0 * 96 + d]        = aq[i].x;
            g_kv[node0 * 192 + d]      = ak[i].x;
            g_kv[node0 * 192 + 96 + d] = av[i].x;
            g_skip[node0 * 96 + d]     = as_[i].x;
        }
        if (node1 < NNODES) {
            g_q[node1 * 96 + d]        = aq[i].y;
            g_kv[node1 * 192 + d]      = ak[i].y;
            g_kv[node1 * 192 + 96 + d] = av[i].y;
            g_skip[node1 * 96 + d]     = as_[i].y;
        }
    }
}

// ---------------- edge aggregation: warp per destination, online softmax ------
// One warp per destination node, We weights in registers, 2-stage software
// pipeline (edge e+1's k/v/edge_attr loads issued before edge e's math).
__global__ void edge_agg(const float* __restrict__ ea, const float* __restrict__ We,
                         float* __restrict__ out) {
    const int warp = (blockIdx.x * blockDim.x + threadIdx.x) >> 5;
    const int lane = threadIdx.x & 31;
    if (warp >= NNODES) return;
    const int n = warp;

    // per-lane We columns: we[h][r] = We[r*96 + h*32 + lane]
    float we[NHEADS][4];
#pragma unroll
    for (int h = 0; h < NHEADS; h++)
#pragma unroll
        for (int r = 0; r < 4; r++)
            we[h][r] = We[r * 96 + h * 32 + lane];

    float qh[NHEADS], m[NHEADS], s[NHEADS], acc[NHEADS], skp[NHEADS];
#pragma unroll
    for (int h = 0; h < NHEADS; h++) {
        qh[h]  = g_q[n * 96 + h * 32 + lane];
        skp[h] = g_skip[n * 96 + h * 32 + lane];
        m[h] = -1e30f; s[h] = 0.f; acc[h] = 0.f;
    }

    const int e0 = g_off[n], e1 = g_off[n + 1];
    const float invs = 0.17677669529663687f;  // 1/sqrt(32)

    // ---- pipeline stage registers (scalar k/v + edge attr) ----
    float4 eav;
    float kk[NHEADS], vv[NHEADS];

    auto load_edge = [&](int e, float4& _eav, float* _k, float* _v) {
        int2 se = g_edges[e];
        const float* kvp = g_kv + (long)se.x * 192;
        _eav = reinterpret_cast<const float4*>(ea)[se.y];
#pragma unroll
        for (int h = 0; h < NHEADS; h++) {
            int di = h * 32 + lane;
            _k[h] = __ldg(kvp + di);
            _v[h] = __ldg(kvp + 96 + di);
        }
    };

    if (e0 < e1) load_edge(e0, eav, kk, vv);

    for (int e = e0; e < e1; e++) {
        // prefetch next edge's payload before consuming current
        float4 n_eav;
        float n_k[NHEADS], n_v[NHEADS];
        if (e + 1 < e1) load_edge(e + 1, n_eav, n_k, n_v);

#pragma unroll
        for (int h = 0; h < NHEADS; h++) {
            float eev = eav.x * we[h][0] + eav.y * we[h][1] +
                        eav.z * we[h][2] + eav.w * we[h][3];
            float kval = kk[h] + eev;
            float vval = vv[h] + eev;
            float p = qh[h] * kval;
            p += __shfl_xor_sync(0xffffffffu, p, 16);
            p += __shfl_xor_sync(0xffffffffu, p, 8);
            p += __shfl_xor_sync(0xffffffffu, p, 4);
            p += __shfl_xor_sync(0xffffffffu, p, 2);
            p += __shfl_xor_sync(0xffffffffu, p, 1);
            float logit = p * invs;
            float nm = fmaxf(m[h], logit);
            float c  = __expf(m[h] - nm);   // 1 if no new max; 0 on first edge
            float pe = __expf(logit - nm);
            s[h]   = s[h] * c + pe;
            acc[h] = acc[h] * c + pe * vval;
            m[h] = nm;
        }

        eav = n_eav;
#pragma unroll
        for (int h = 0; h < NHEADS; h++) { kk[h] = n_k[h]; vv[h] = n_v[h]; }
    }

#pragma unroll
    for (int h = 0; h < NHEADS; h++) {
        float o = acc[h] / (s[h] + 1e-16f) + skp[h];
        out[n * 96 + h * 32 + lane] = tanhf(o);
    }
}

// ---------------- launch ----------------
extern "C" void kernel_launch(void* const* d_in, const int* in_sizes, int n_in,
                              void* d_out, int out_size) {
    const float* x   = (const float*)d_in[0];
    const int*   ei  = (const int*)d_in[1];
    const float* ea  = (const float*)d_in[2];
    const float* W1  = (const float*)d_in[3];
    const float* b1  = (const float*)d_in[4];
    const float* Wq1 = (const float*)d_in[5];
    const float* bq1 = (const float*)d_in[6];
    const float* Wk1 = (const float*)d_in[7];
    const float* bk1 = (const float*)d_in[8];
    const float* Wv1 = (const float*)d_in[9];
    const float* bv1 = (const float*)d_in[10];
    const float* We1 = (const float*)d_in[11];
    const float* Ws1 = (const float*)d_in[12];
    const float* bs1 = (const float*)d_in[13];
    const float* Wq2 = (const float*)d_in[14];
    const float* bq2 = (const float*)d_in[15];
    const float* Wk2 = (const float*)d_in[16];
    const float* bk2 = (const float*)d_in[17];
    const float* Wv2 = (const float*)d_in[18];
    const float* bv2 = (const float*)d_in[19];
    const float* We2 = (const float*)d_in[20];
    const float* Ws2 = (const float*)d_in[21];
    const float* bs2 = (const float*)d_in[22];
    float* out = (float*)d_out;

    float* h0; cudaGetSymbolAddress((void**)&h0, g_h0);
    float* h1; cudaGetSymbolAddress((void**)&h1, g_h1);

    const int nScanBlocks = (NNODES + 1023) / 1024;

    // pre-MLP
    pre_mlp<<<(NNODES * 8 + 255) / 256, 256>>>(x, W1, b1);

    // counting sort by dst (CSR build)
    zero_deg<<<(NNODES + 255) / 256, 256>>>();
    hist_kernel<<<(NE + 255) / 256, 256>>>(ei);
    scan_block<<<nScanBlocks, 1024>>>();
    scan_bsum<<<1, 64>>>(nScanBlocks);
    scan_add<<<(NNODES + 255) / 256, 256>>>();
    scatter_kernel<<<(NE + 255) / 256, 256>>>(ei);

    dim3 tfb(96, 2);
    const int nTfBlocks = (NNODES + 31) / 32;
    const int nAggBlocks = (NNODES * 32 + 255) / 256;

    // layer 1
    node_transform<8><<<nTfBlocks, tfb>>>(h0, Wq1, bq1, Wk1, bk1, Wv1, bv1, Ws1, bs1);
    edge_agg<<<nAggBlocks, 256>>>(ea, We1, h1);

    // layer 2
    node_transform<96><<<nTfBlocks, tfb>>>(h1, Wq2, bq2, Wk2, bk2, Wv2, bv2, Ws2, bs2);
    edge_agg<<<nAggBlocks, 256>>>(ea, We2, out);
}